// round 1
// baseline (speedup 1.0000x reference)
#include <cuda_runtime.h>
#include <math.h>

// Problem constants
#define NT 256           // threads per block, pass 1
#define GMAX 64          // number of ground-truth boxes
#define MAXB 1024        // max blocks in pass 1 (R/NT = 512 for R=131072)

// iou > 0.8  <=>  inter > (0.8/1.8)*(ar+ag)
// iou < 0.3  <=>  inter < (0.3/1.3)*(ar+ag)
#define SPOS (0.8f / 1.8f)
#define SNEG (0.3f / 1.3f)

// Per-block partials (no device-memory allocation allowed -> __device__ globals)
__device__ unsigned long long g_keys[MAXB * GMAX];
__device__ int   g_posc[MAXB];
__device__ int   g_negc[MAXB];
__device__ int   g_cnt [MAXB];
__device__ float g_psum[MAXB];
__device__ float g_rsum[MAXB];

__device__ __forceinline__ float sl1(float d) {
    return (d < 1.0f) ? 0.5f * d * d : d - 0.5f;
}

// ---------------------------------------------------------------------------
// Pass 1: one thread per region. Computes per-region labels (hasPos / allNeg),
// per-gt running argmax of IoU (shared packed key + filtered atomicMax),
// and smooth-L1 contributions for pairs with iou > 0.8 (rare).
// ---------------------------------------------------------------------------
__global__ __launch_bounds__(NT)
void rpn_pass1(const float* __restrict__ scores,
               const float4* __restrict__ regions,
               const float4* __restrict__ anchors,
               const float4* __restrict__ gts,
               int R)
{
    __shared__ float4 s_gt[GMAX];
    __shared__ float  s_ag[GMAX];
    __shared__ unsigned long long s_key[GMAX];
    __shared__ int   s_posc, s_negc, s_cnt;
    __shared__ float s_psum, s_rsum;

    const int tid = threadIdx.x;
    if (tid < GMAX) {
        float4 b = gts[tid];
        s_gt[tid] = b;
        s_ag[tid] = (b.z - b.x) * (b.w - b.y);
        // init key: iou = 0.0 (high word 0), index r = 0 (low word 0x7FFFFFFF)
        s_key[tid] = 0x7FFFFFFFull;
    }
    if (tid == 0) { s_posc = 0; s_negc = 0; s_cnt = 0; s_psum = 0.f; s_rsum = 0.f; }
    __syncthreads();

    const int r = blockIdx.x * NT + tid;
    if (r < R) {
        const float4 rb = regions[r];
        const float  ar = (rb.z - rb.x) * (rb.w - rb.y);

        bool hasPos = false;
        bool allNeg = true;

        #pragma unroll 16
        for (int g = 0; g < GMAX; ++g) {
            const float4 gb = s_gt[g];
            float dx = fminf(rb.z, gb.z) - fmaxf(rb.x, gb.x);
            float dy = fminf(rb.w, gb.w) - fmaxf(rb.y, gb.y);
            dx = fmaxf(dx, 0.0f);
            dy = fmaxf(dy, 0.0f);
            const float inter = dx * dy;
            const float sum   = ar + s_ag[g];

            hasPos = hasPos || (inter > SPOS * sum);
            allNeg = allNeg && (inter < SNEG * sum);

            // argmax filter without division: iou > cur  <=>  inter > cur*denom
            const float denom = sum - inter;   // always > 0
            const unsigned long long curk =
                *(volatile unsigned long long*)&s_key[g];
            const float cur = __uint_as_float((unsigned)(curk >> 32));
            if (inter > cur * denom) {
                const float iou = inter / denom;
                const unsigned long long key =
                    ((unsigned long long)__float_as_uint(iou) << 32) |
                    (unsigned long long)(0x7FFFFFFFu - (unsigned)r);
                atomicMax(&s_key[g], key);
            }
        }

        if (allNeg) atomicAdd(&s_negc, 1);
        if (hasPos) {
            atomicAdd(&s_posc, 1);
            atomicAdd(&s_psum, scores[r]);

            // regression pairs with iou > 0.8 (anchors cancel except aw, ah)
            const float4 ab  = anchors[r];
            const float  aw  = ab.z - ab.x;
            const float  ah  = ab.w - ab.y;
            const float  rcx = (rb.x + rb.z) * 0.5f;
            const float  rcy = (rb.y + rb.w) * 0.5f;
            const float  lrw = logf(rb.z - rb.x);
            const float  lrh = logf(rb.w - rb.y);

            float rsum = 0.0f;
            int   c    = 0;
            for (int g = 0; g < GMAX; ++g) {
                const float4 gb = s_gt[g];
                float dx = fminf(rb.z, gb.z) - fmaxf(rb.x, gb.x);
                float dy = fminf(rb.w, gb.w) - fmaxf(rb.y, gb.y);
                dx = fmaxf(dx, 0.0f);
                dy = fmaxf(dy, 0.0f);
                const float inter = dx * dy;
                const float sum   = ar + s_ag[g];
                if (inter > SPOS * sum) {
                    const float gcx = (gb.x + gb.z) * 0.5f;
                    const float gcy = (gb.y + gb.w) * 0.5f;
                    const float d0 = fabsf(rcx - gcx) / aw;
                    const float d1 = fabsf(rcy - gcy) / ah;
                    const float d2 = fabsf(lrw - logf(gb.z - gb.x));
                    const float d3 = fabsf(lrh - logf(gb.w - gb.y));
                    rsum += 0.25f * (sl1(d0) + sl1(d1) + sl1(d2) + sl1(d3));
                    ++c;
                }
            }
            if (c) { atomicAdd(&s_rsum, rsum); atomicAdd(&s_cnt, c); }
        }
    }

    __syncthreads();
    if (tid < GMAX) g_keys[blockIdx.x * GMAX + tid] = s_key[tid];
    if (tid == 0) {
        g_posc[blockIdx.x] = s_posc;
        g_negc[blockIdx.x] = s_negc;
        g_cnt [blockIdx.x] = s_cnt;
        g_psum[blockIdx.x] = s_psum;
        g_rsum[blockIdx.x] = s_rsum;
    }
}

// ---------------------------------------------------------------------------
// Pass 2: single block. Reduce block partials, resolve argmax (scatter
// rs[best[g], g] = 1), dedupe best rows, finalize the loss.
// ---------------------------------------------------------------------------
__global__ __launch_bounds__(256)
void rpn_pass2(const float* __restrict__ scores,
               const float4* __restrict__ regions,
               const float4* __restrict__ anchors,
               const float4* __restrict__ gts,
               int R, int NB,
               float* __restrict__ out, int out_size)
{
    __shared__ float4 s_gt[GMAX];
    __shared__ float  s_ag[GMAX];
    __shared__ int    s_best[GMAX];
    __shared__ int    s_posc, s_negc, s_cnt, s_padd, s_nsub, s_cadd;
    __shared__ float  s_psum, s_rsum, s_psadd, s_radd;

    const int tid = threadIdx.x;
    if (tid == 0) {
        s_posc = 0; s_negc = 0; s_cnt = 0;
        s_padd = 0; s_nsub = 0; s_cadd = 0;
        s_psum = 0.f; s_rsum = 0.f; s_psadd = 0.f; s_radd = 0.f;
    }
    if (tid < GMAX) {
        float4 b = gts[tid];
        s_gt[tid] = b;
        s_ag[tid] = (b.z - b.x) * (b.w - b.y);
    }
    __syncthreads();

    // reduce per-block partials
    {
        int   pc = 0, nc = 0, ct = 0;
        float ps = 0.f, rs = 0.f;
        for (int b = tid; b < NB; b += blockDim.x) {
            pc += g_posc[b]; nc += g_negc[b]; ct += g_cnt[b];
            ps += g_psum[b]; rs += g_rsum[b];
        }
        if (pc) atomicAdd(&s_posc, pc);
        if (nc) atomicAdd(&s_negc, nc);
        if (ct) atomicAdd(&s_cnt, ct);
        atomicAdd(&s_psum, ps);
        atomicAdd(&s_rsum, rs);
    }

    // global argmax per gt
    if (tid < GMAX) {
        unsigned long long best = 0ull;
        for (int b = 0; b < NB; ++b) {
            const unsigned long long k = g_keys[b * GMAX + tid];
            if (k > best) best = k;
        }
        s_best[tid] = (int)(0x7FFFFFFFu - (unsigned)(best & 0xFFFFFFFFull));
    }
    __syncthreads();

    // scatter fixups
    if (tid < GMAX) {
        const int g = tid;
        const int r = s_best[g];

        bool owner = true;                      // first gt that uses this row
        for (int j = 0; j < g; ++j)
            if (s_best[j] == r) owner = false;

        const float4 rb = regions[r];
        const float  ar = (rb.z - rb.x) * (rb.w - rb.y);

        bool hasPos = false, allNeg = true;
        float inter_g = 0.f, sum_g = 0.f;
        for (int j = 0; j < GMAX; ++j) {
            const float4 gb = s_gt[j];
            float dx = fminf(rb.z, gb.z) - fmaxf(rb.x, gb.x);
            float dy = fminf(rb.w, gb.w) - fmaxf(rb.y, gb.y);
            dx = fmaxf(dx, 0.0f);
            dy = fmaxf(dy, 0.0f);
            const float inter = dx * dy;
            const float sum   = ar + s_ag[j];
            hasPos = hasPos || (inter > SPOS * sum);
            allNeg = allNeg && (inter < SNEG * sum);
            if (j == g) { inter_g = inter; sum_g = sum; }
        }

        if (owner) {
            if (!hasPos) {                      // row becomes pos via scatter
                atomicAdd(&s_padd, 1);
                atomicAdd(&s_psadd, scores[r]);
            }
            if (allNeg) atomicAdd(&s_nsub, 1); // was counted neg in pass 1
        }

        // scatter pair not already counted as iou>0.8 pair
        if (!(inter_g > SPOS * sum_g)) {
            const float4 ab  = anchors[r];
            const float  aw  = ab.z - ab.x;
            const float  ah  = ab.w - ab.y;
            const float4 gb  = s_gt[g];
            const float  rcx = (rb.x + rb.z) * 0.5f;
            const float  rcy = (rb.y + rb.w) * 0.5f;
            const float  gcx = (gb.x + gb.z) * 0.5f;
            const float  gcy = (gb.y + gb.w) * 0.5f;
            const float  d0  = fabsf(rcx - gcx) / aw;
            const float  d1  = fabsf(rcy - gcy) / ah;
            const float  d2  = fabsf(logf(rb.z - rb.x) - logf(gb.z - gb.x));
            const float  d3  = fabsf(logf(rb.w - rb.y) - logf(gb.w - gb.y));
            atomicAdd(&s_radd, 0.25f * (sl1(d0) + sl1(d1) + sl1(d2) + sl1(d3)));
            atomicAdd(&s_cadd, 1);
        }
    }
    __syncthreads();

    if (tid == 0) {
        const double n_pos = (double)(s_posc + s_padd);
        const double n_neg = (double)(s_negc - s_nsub);
        const double n     = n_pos + n_neg;

        const double C1  = 0.3132616875182228;   // log1p(exp(-1))
        const double LN2 = 0.6931471805599453;

        const double fpos_sum = n_pos * (1.0 + C1) - (double)(s_psum + s_psadd);
        const double cls      = (fpos_sum + n_neg * LN2) / n;

        const double reg = (double)(s_rsum + s_radd);
        const double cnt = (double)(s_cnt + s_cadd);

        const double loss = cls / n + 10.0 * reg / cnt;

        out[0] = (float)loss;
        if (out_size > 1) out[1] = (float)s_best[GMAX - 1];  // max_iou_idx = best[-1]
    }
}

// ---------------------------------------------------------------------------
// Launch
// ---------------------------------------------------------------------------
extern "C" void kernel_launch(void* const* d_in, const int* in_sizes, int n_in,
                              void* d_out, int out_size)
{
    const float*  scores  = (const float*) d_in[0];
    const float4* regions = (const float4*)d_in[1];
    const float4* anchors = (const float4*)d_in[2];
    const float4* gts     = (const float4*)d_in[3];
    const int R  = in_sizes[0];
    const int NB = (R + NT - 1) / NT;

    rpn_pass1<<<NB, NT>>>(scores, regions, anchors, gts, R);
    rpn_pass2<<<1, 256>>>(scores, regions, anchors, gts, R, NB,
                          (float*)d_out, out_size);
}

// round 2
// speedup vs baseline: 1.9969x; 1.9969x over previous
#include <cuda_runtime.h>
#include <math.h>

// Problem constants
#define NT 256           // threads per block, pass 1
#define GMAX 64          // number of ground-truth boxes

// iou > 0.8  <=>  inter > (0.8/1.8)*(ar+ag)
// iou < 0.3  <=>  inter < (0.3/1.3)*(ar+ag)
#define SPOS (0.8f / 1.8f)
#define SNEG (0.3f / 1.3f)

// Global accumulators. Zero-initialized at module load; rpn_pass2 re-zeroes
// them at the end of every call, so each kernel_launch (correctness run and
// every graph replay) starts from the zeroed state.
// Key encoding: (iou_bits << 32) | (0xFFFFFFFF - r). key==0 <=> no pair with
// inter>0 anywhere  =>  argmax index 0 (matches jnp.argmax on all-equal row).
__device__ unsigned long long g_key[GMAX];   // zero-init
__device__ int   g_posc;                     // zero-init
__device__ int   g_negc;
__device__ int   g_cnt;
__device__ float g_psum;
__device__ float g_rsum;

__device__ __forceinline__ float sl1(float d) {
    return (d < 1.0f) ? 0.5f * d * d : d - 0.5f;
}

// ---------------------------------------------------------------------------
// Pass 1: one thread per region. Per-region labels (hasPos / allNeg),
// per-gt running argmax of IoU (shared packed key + filtered atomicMax),
// smooth-L1 contributions for pairs with iou > 0.8 (rare). Block-end merges
// go straight to global atomics (RED) — no per-block arrays.
// ---------------------------------------------------------------------------
__global__ __launch_bounds__(NT)
void rpn_pass1(const float* __restrict__ scores,
               const float4* __restrict__ regions,
               const float4* __restrict__ anchors,
               const float4* __restrict__ gts,
               int R)
{
    __shared__ float4 s_gt[GMAX];
    __shared__ float  s_ag[GMAX];
    __shared__ unsigned long long s_key[GMAX];
    __shared__ int   s_posc, s_negc, s_cnt;
    __shared__ float s_psum, s_rsum;

    const int tid = threadIdx.x;
    if (tid < GMAX) {
        float4 b = gts[tid];
        s_gt[tid] = b;
        s_ag[tid] = (b.z - b.x) * (b.w - b.y);
        s_key[tid] = 0ull;   // iou = 0; decodes specially (r=0) if never beaten
    }
    if (tid == 0) { s_posc = 0; s_negc = 0; s_cnt = 0; s_psum = 0.f; s_rsum = 0.f; }
    __syncthreads();

    const int r = blockIdx.x * NT + tid;
    if (r < R) {
        const float4 rb = regions[r];
        const float  ar = (rb.z - rb.x) * (rb.w - rb.y);

        bool hasPos = false;
        bool allNeg = true;

        #pragma unroll 16
        for (int g = 0; g < GMAX; ++g) {
            const float4 gb = s_gt[g];
            float dx = fminf(rb.z, gb.z) - fmaxf(rb.x, gb.x);
            float dy = fminf(rb.w, gb.w) - fmaxf(rb.y, gb.y);
            dx = fmaxf(dx, 0.0f);
            dy = fmaxf(dy, 0.0f);
            const float inter = dx * dy;
            const float sum   = ar + s_ag[g];

            hasPos = hasPos || (inter > SPOS * sum);
            allNeg = allNeg && (inter < SNEG * sum);

            // argmax filter without division: iou > cur  <=>  inter > cur*denom
            const float denom = sum - inter;   // always > 0
            const unsigned long long curk =
                *(volatile unsigned long long*)&s_key[g];
            const float cur = __uint_as_float((unsigned)(curk >> 32));
            if (inter > cur * denom) {
                const float iou = inter / denom;
                const unsigned long long key =
                    ((unsigned long long)__float_as_uint(iou) << 32) |
                    (unsigned long long)(0xFFFFFFFFu - (unsigned)r);
                atomicMax(&s_key[g], key);
            }
        }

        if (allNeg) atomicAdd(&s_negc, 1);
        if (hasPos) {
            atomicAdd(&s_posc, 1);
            atomicAdd(&s_psum, scores[r]);

            // regression pairs with iou > 0.8 (anchors cancel except aw, ah)
            const float4 ab  = anchors[r];
            const float  aw  = ab.z - ab.x;
            const float  ah  = ab.w - ab.y;
            const float  rcx = (rb.x + rb.z) * 0.5f;
            const float  rcy = (rb.y + rb.w) * 0.5f;
            const float  lrw = logf(rb.z - rb.x);
            const float  lrh = logf(rb.w - rb.y);

            float rsum = 0.0f;
            int   c    = 0;
            for (int g = 0; g < GMAX; ++g) {
                const float4 gb = s_gt[g];
                float dx = fminf(rb.z, gb.z) - fmaxf(rb.x, gb.x);
                float dy = fminf(rb.w, gb.w) - fmaxf(rb.y, gb.y);
                dx = fmaxf(dx, 0.0f);
                dy = fmaxf(dy, 0.0f);
                const float inter = dx * dy;
                const float sum   = ar + s_ag[g];
                if (inter > SPOS * sum) {
                    const float gcx = (gb.x + gb.z) * 0.5f;
                    const float gcy = (gb.y + gb.w) * 0.5f;
                    const float d0 = fabsf(rcx - gcx) / aw;
                    const float d1 = fabsf(rcy - gcy) / ah;
                    const float d2 = fabsf(lrw - logf(gb.z - gb.x));
                    const float d3 = fabsf(lrh - logf(gb.w - gb.y));
                    rsum += 0.25f * (sl1(d0) + sl1(d1) + sl1(d2) + sl1(d3));
                    ++c;
                }
            }
            if (c) { atomicAdd(&s_rsum, rsum); atomicAdd(&s_cnt, c); }
        }
    }

    __syncthreads();
    // Block-end merge straight into global accumulators (no-return -> RED).
    if (tid < GMAX) {
        const unsigned long long k = s_key[tid];
        if (k) atomicMax(&g_key[tid], k);
    }
    if (tid == 0) {
        if (s_posc) { atomicAdd(&g_posc, s_posc); atomicAdd(&g_psum, s_psum); }
        if (s_negc)   atomicAdd(&g_negc, s_negc);
        if (s_cnt)  { atomicAdd(&g_cnt, s_cnt);   atomicAdd(&g_rsum, s_rsum); }
    }
}

// ---------------------------------------------------------------------------
// Pass 2: 64 threads. Resolve argmax scatter (rs[best[g], g] = 1), dedupe
// best rows, finalize the loss, then reset globals for the next call.
// ---------------------------------------------------------------------------
__global__ __launch_bounds__(64)
void rpn_pass2(const float* __restrict__ scores,
               const float4* __restrict__ regions,
               const float4* __restrict__ anchors,
               const float4* __restrict__ gts,
               float* __restrict__ out, int out_size)
{
    __shared__ float4 s_gt[GMAX];
    __shared__ float  s_ag[GMAX];
    __shared__ int    s_best[GMAX];
    __shared__ int    s_padd, s_nsub, s_cadd;
    __shared__ float  s_psadd, s_radd;

    const int g = threadIdx.x;   // 0..63
    if (g == 0) { s_padd = 0; s_nsub = 0; s_cadd = 0; s_psadd = 0.f; s_radd = 0.f; }

    {
        float4 b = gts[g];
        s_gt[g] = b;
        s_ag[g] = (b.z - b.x) * (b.w - b.y);
        const unsigned long long k = g_key[g];
        s_best[g] = (k == 0ull) ? 0
                  : (int)(0xFFFFFFFFu - (unsigned)(k & 0xFFFFFFFFull));
    }
    __syncthreads();

    // scatter fixups
    {
        const int r = s_best[g];

        bool owner = true;                      // first gt that uses this row
        for (int j = 0; j < g; ++j)
            if (s_best[j] == r) owner = false;

        const float4 rb = regions[r];
        const float  ar = (rb.z - rb.x) * (rb.w - rb.y);

        bool hasPos = false, allNeg = true;
        float inter_g = 0.f, sum_g = 0.f;
        for (int j = 0; j < GMAX; ++j) {
            const float4 gb = s_gt[j];
            float dx = fminf(rb.z, gb.z) - fmaxf(rb.x, gb.x);
            float dy = fminf(rb.w, gb.w) - fmaxf(rb.y, gb.y);
            dx = fmaxf(dx, 0.0f);
            dy = fmaxf(dy, 0.0f);
            const float inter = dx * dy;
            const float sum   = ar + s_ag[j];
            hasPos = hasPos || (inter > SPOS * sum);
            allNeg = allNeg && (inter < SNEG * sum);
            if (j == g) { inter_g = inter; sum_g = sum; }
        }

        if (owner) {
            if (!hasPos) {                      // row becomes pos via scatter
                atomicAdd(&s_padd, 1);
                atomicAdd(&s_psadd, scores[r]);
            }
            if (allNeg) atomicAdd(&s_nsub, 1); // was counted neg in pass 1
        }

        // scatter pair not already counted as an iou>0.8 pair
        if (!(inter_g > SPOS * sum_g)) {
            const float4 ab  = anchors[r];
            const float  aw  = ab.z - ab.x;
            const float  ah  = ab.w - ab.y;
            const float4 gb  = s_gt[g];
            const float  rcx = (rb.x + rb.z) * 0.5f;
            const float  rcy = (rb.y + rb.w) * 0.5f;
            const float  gcx = (gb.x + gb.z) * 0.5f;
            const float  gcy = (gb.y + gb.w) * 0.5f;
            const float  d0  = fabsf(rcx - gcx) / aw;
            const float  d1  = fabsf(rcy - gcy) / ah;
            const float  d2  = fabsf(logf(rb.z - rb.x) - logf(gb.z - gb.x));
            const float  d3  = fabsf(logf(rb.w - rb.y) - logf(gb.w - gb.y));
            atomicAdd(&s_radd, 0.25f * (sl1(d0) + sl1(d1) + sl1(d2) + sl1(d3)));
            atomicAdd(&s_cadd, 1);
        }
    }
    __syncthreads();

    if (g == 0) {
        const double n_pos = (double)(g_posc + s_padd);
        const double n_neg = (double)(g_negc - s_nsub);
        const double n     = n_pos + n_neg;

        const double C1  = 0.3132616875182228;   // log1p(exp(-1))
        const double LN2 = 0.6931471805599453;

        const double fpos_sum = n_pos * (1.0 + C1) - (double)(g_psum + s_psadd);
        const double cls      = (fpos_sum + n_neg * LN2) / n;

        const double reg = (double)(g_rsum + s_radd);
        const double cnt = (double)(g_cnt + s_cadd);

        const double loss = cls / n + 10.0 * reg / cnt;

        out[0] = (float)loss;
        if (out_size > 1) out[1] = (float)s_best[GMAX - 1];  // max_iou_idx
    }

    // Reset globals for the next call (all reads above are done).
    __syncthreads();
    g_key[g] = 0ull;
    if (g == 0) {
        g_posc = 0; g_negc = 0; g_cnt = 0;
        g_psum = 0.f; g_rsum = 0.f;
    }
}

// ---------------------------------------------------------------------------
// Launch
// ---------------------------------------------------------------------------
extern "C" void kernel_launch(void* const* d_in, const int* in_sizes, int n_in,
                              void* d_out, int out_size)
{
    const float*  scores  = (const float*) d_in[0];
    const float4* regions = (const float4*)d_in[1];
    const float4* anchors = (const float4*)d_in[2];
    const float4* gts     = (const float4*)d_in[3];
    const int R  = in_sizes[0];
    const int NB = (R + NT - 1) / NT;

    rpn_pass1<<<NB, NT>>>(scores, regions, anchors, gts, R);
    rpn_pass2<<<1, 64>>>(scores, regions, anchors, gts,
                         (float*)d_out, out_size);
}